// round 16
// baseline (speedup 1.0000x reference)
#include <cuda_runtime.h>
#include <cuda_bf16.h>
#include <cuda_fp16.h>
#include <math_constants.h>
#include <cstdint>

#define S_LEN 4096
#define EMB   768
#define NHEAD 12
#define HD    64
#define WIN   256

// Projected Q/K/V in fp16, laid out (S, H*D) contiguous.
__device__ __half g_qh[S_LEN * EMB];
__device__ __half g_kh[S_LEN * EMB];
__device__ __half g_vh[S_LEN * EMB];

// Pre-permuted fp16 operands for the QKV GEMM (fragment-native layouts).
#define XA_UNITS (32 * 24 * 512)
__device__ uint4 g_xa[XA_UNITS];
#define WP_UNITS (3 * 12 * 24 * 256)
__device__ uint4 g_wp[WP_UNITS];

__device__ __forceinline__ void mma_f16(float c[4], const unsigned a[4],
                                        unsigned b0, unsigned b1) {
    asm volatile(
        "mma.sync.aligned.m16n8k16.row.col.f32.f16.f16.f32 "
        "{%0,%1,%2,%3}, {%4,%5,%6,%7}, {%8,%9}, {%0,%1,%2,%3};"
        : "+f"(c[0]), "+f"(c[1]), "+f"(c[2]), "+f"(c[3])
        : "r"(a[0]), "r"(a[1]), "r"(a[2]), "r"(a[3]), "r"(b0), "r"(b1));
}

__device__ __forceinline__ unsigned packh2(float lo, float hi) {
    __half2 h = __float22half2_rn(make_float2(lo, hi));
    return *reinterpret_cast<unsigned*>(&h);
}

#define LDMATRIX_X4(r0, r1, r2, r3, addr)                                      \
    asm volatile("ldmatrix.sync.aligned.m8n8.x4.shared.b16 {%0,%1,%2,%3}, [%4];" \
                 : "=r"(r0), "=r"(r1), "=r"(r2), "=r"(r3) : "r"(addr))

#define LDMATRIX_X4_T(r0, r1, r2, r3, addr)                                    \
    asm volatile("ldmatrix.sync.aligned.m8n8.x4.trans.shared.b16 {%0,%1,%2,%3}, [%4];" \
                 : "=r"(r0), "=r"(r1), "=r"(r2), "=r"(r3) : "r"(addr))

// ---------------------------------------------------------------------------
// Fused prep: z=0 -> X to A-frag layout; z=1..3 -> Wq/Wk/Wv to B-frag layout.
// ---------------------------------------------------------------------------
__global__ __launch_bounds__(256) void prep_kernel(
    const float* __restrict__ X,
    const float* __restrict__ Wq, const float* __restrict__ Wk,
    const float* __restrict__ Wv)
{
    if (blockIdx.z == 0) {
        int u = blockIdx.x * 256 + threadIdx.x;
        if (u >= XA_UNITS) return;
        int tg   = u & 3;
        int g    = (u >> 2) & 7;
        int kk2  = (u >> 5) & 1;
        int m16  = (u >> 6) & 7;
        int tile = u >> 9;
        int kb   = tile % 24;
        int mb   = tile / 24;
        int r0 = mb * 128 + m16 * 16 + g;
        int c0 = kb * 32 + kk2 * 16 + tg * 2;

        float2 x00 = *reinterpret_cast<const float2*>(&X[(size_t)r0 * EMB + c0]);
        float2 x10 = *reinterpret_cast<const float2*>(&X[(size_t)(r0 + 8) * EMB + c0]);
        float2 x01 = *reinterpret_cast<const float2*>(&X[(size_t)r0 * EMB + c0 + 8]);
        float2 x11 = *reinterpret_cast<const float2*>(&X[(size_t)(r0 + 8) * EMB + c0 + 8]);

        uint4 w;
        w.x = packh2(x00.x, x00.y);
        w.y = packh2(x10.x, x10.y);
        w.z = packh2(x01.x, x01.y);
        w.w = packh2(x11.x, x11.y);
        g_xa[u] = w;
    } else {
        const int which = blockIdx.z - 1;
        const float* W = (which == 0) ? Wq : (which == 1) ? Wk : Wv;
        int u = blockIdx.x * 256 + threadIdx.x;
        const int perW = 12 * 24 * 256;
        if (u >= perW) return;
        int tg   = u & 3;
        int g    = (u >> 2) & 7;
        int wn2  = (u >> 5) & 1;
        int half = (u >> 6) & 1;
        int kk2  = (u >> 7) & 1;
        int tile = u >> 8;
        int kb   = tile % 24;
        int nb   = tile / 24;
        int c0 = kb * 32 + kk2 * 16 + tg * 2 + half * 8;
        int n0 = nb * 64 + wn2 * 32 + g;

        const float* r0 = W + (size_t)c0 * EMB;
        const float* r1 = W + (size_t)(c0 + 1) * EMB;
        uint4 w;
        w.x = packh2(r0[n0     ], r1[n0     ]);
        w.y = packh2(r0[n0 +  8], r1[n0 +  8]);
        w.z = packh2(r0[n0 + 16], r1[n0 + 16]);
        w.w = packh2(r0[n0 + 24], r1[n0 + 24]);
        g_wp[which * perW + u] = w;
    }
}

// ---------------------------------------------------------------------------
// Fused QKV fp16 GEMM, zero smem, fragment-native gmem operands (L2-resident).
// CTA tile 128x128: 8 warps = 2m x 4n, warp tile 64x32, C = 64 regs/thread.
// Grid (6 nc, 32 mb, 3 which). Epilogue writes fp16 to g_qh/g_kh/g_vh.
// ---------------------------------------------------------------------------
__global__ __launch_bounds__(256) void qkv_gemm_kernel(
    const float* __restrict__ bq_, const float* __restrict__ bk_,
    const float* __restrict__ bv_)
{
    const int which = blockIdx.z;
    const float* bias = (which == 0) ? bq_ : (which == 1) ? bk_ : bv_;
    __half* out       = (which == 0) ? g_qh : (which == 1) ? g_kh : g_vh;
    const float scale = (which == 0) ? 0.125f : 1.0f;

    const int nc   = blockIdx.x;     // 128-col block (0..5)
    const int mb   = blockIdx.y;     // 128-row block (0..31)
    const int t    = threadIdx.x;
    const int lane = t & 31;
    const int wid  = t >> 5;
    const int wm   = wid & 1;        // m-group (64 rows)
    const int wn4  = wid >> 1;       // n-group (32 cols), 0..3
    const int nbl  = wn4 >> 1;       // 64-col sub-block within CTA
    const int wn2  = wn4 & 1;        // 32-col half within nb
    const int g    = lane >> 2;
    const int tg   = lane & 3;

    const uint4* xa = g_xa + (size_t)(mb * 24) * 512;
    const uint4* wp = g_wp + ((size_t)(which * 12 + nc * 2 + nbl) * 24) * 256;

    float c[4][4][4];
#pragma unroll
    for (int mi = 0; mi < 4; mi++)
#pragma unroll
        for (int ni = 0; ni < 4; ni++)
#pragma unroll
            for (int j = 0; j < 4; j++) c[mi][ni][j] = 0.f;

    int offA[2][4], offB[2][2];
#pragma unroll
    for (int kk2 = 0; kk2 < 2; kk2++) {
#pragma unroll
        for (int mi = 0; mi < 4; mi++)
            offA[kk2][mi] = (((wm * 4 + mi) * 2 + kk2) << 5) + lane;
#pragma unroll
        for (int hh = 0; hh < 2; hh++)
            offB[kk2][hh] = (((kk2 * 2 + hh) * 2 + wn2) << 5) + lane;
    }

#pragma unroll 2
    for (int kb = 0; kb < 24; kb++) {
        const uint4* ax = xa + kb * 512;
        const uint4* bx = wp + kb * 256;
#pragma unroll
        for (int kk2 = 0; kk2 < 2; kk2++) {
            uint4 afr[4];
#pragma unroll
            for (int mi = 0; mi < 4; mi++) afr[mi] = ax[offA[kk2][mi]];
            uint4 b0 = bx[offB[kk2][0]];
            uint4 b1 = bx[offB[kk2][1]];
            unsigned b0a[4] = {b0.x, b0.y, b0.z, b0.w};
            unsigned b1a[4] = {b1.x, b1.y, b1.z, b1.w};
#pragma unroll
            for (int mi = 0; mi < 4; mi++) {
                const unsigned* ar = reinterpret_cast<const unsigned*>(&afr[mi]);
#pragma unroll
                for (int ni = 0; ni < 4; ni++)
                    mma_f16(c[mi][ni], ar, b0a[ni], b1a[ni]);
            }
        }
    }

    const int bm = mb * 128;
    const int bn = nc * 128 + wn4 * 32;
#pragma unroll
    for (int mi = 0; mi < 4; mi++)
#pragma unroll
        for (int ni = 0; ni < 4; ni++) {
            int row = bm + wm * 64 + mi * 16 + g;
            int col = bn + ni * 8 + 2 * tg;
            float b0 = bias[col], b1 = bias[col + 1];
            unsigned h0 = packh2((c[mi][ni][0] + b0) * scale, (c[mi][ni][1] + b1) * scale);
            unsigned h1 = packh2((c[mi][ni][2] + b0) * scale, (c[mi][ni][3] + b1) * scale);
            *reinterpret_cast<unsigned*>(&out[(size_t)row * EMB + col])       = h0;
            *reinterpret_cast<unsigned*>(&out[(size_t)(row + 8) * EMB + col]) = h1;
        }
}

// ---------------------------------------------------------------------------
// fp16 tensor-core banded flash attention: 64 queries x 1 head per CTA,
// 128 threads; edge specialization (window compares only for c9 == 0/8).
// ---------------------------------------------------------------------------
#define KST 72  // smem row stride in halves

__global__ __launch_bounds__(128) void attn_mma_kernel(
    const float* __restrict__ amask, const unsigned char* __restrict__ imask,
    float* __restrict__ out)
{
    __shared__ __half sQ[64 * KST];
    __shared__ __half sK[2][64 * KST];
    __shared__ __half sV[2][64 * KST];
    __shared__ float  sFM[2][64];

    const int i0   = blockIdx.x * 64;
    const int h    = blockIdx.y;
    const int t    = threadIdx.x;
    const int lane = t & 31;
    const int warp = t >> 5;
    const int g    = lane >> 2;
    const int tg   = lane & 3;
    const float NEG_INF = -CUDART_INF_F;

#pragma unroll
    for (int u = 0; u < 4; u++) {
        int vv = t + u * 128;
        int r = vv >> 3, w = vv & 7;
        uint4 q = *reinterpret_cast<const uint4*>(&g_qh[(size_t)(i0 + r) * EMB + h * HD + w * 8]);
        *reinterpret_cast<uint4*>(&sQ[r * KST + w * 8]) = q;
    }

    auto stageKV = [&](int c9, int buf) {
        int jc0 = i0 - WIN + c9 * 64;
#pragma unroll
        for (int u = 0; u < 4; u++) {
            int vv = t + u * 128;
            int r = vv >> 3, w = vv & 7;
            int jg = jc0 + r;
            bool ok = (jg >= 0 && jg < S_LEN);
            size_t src = ok ? ((size_t)jg * EMB + h * HD + w * 8) : 0;
            int sz = ok ? 16 : 0;
            unsigned kd = (unsigned)__cvta_generic_to_shared(&sK[buf][r * KST + w * 8]);
            unsigned vd = (unsigned)__cvta_generic_to_shared(&sV[buf][r * KST + w * 8]);
            asm volatile("cp.async.cg.shared.global [%0], [%1], 16, %2;"
                         :: "r"(kd), "l"(g_kh + src), "r"(sz));
            asm volatile("cp.async.cg.shared.global [%0], [%1], 16, %2;"
                         :: "r"(vd), "l"(g_vh + src), "r"(sz));
        }
        asm volatile("cp.async.commit_group;");
        if (t < 64) {
            int jg = jc0 + t;
            float fm;
            if (jg < 0 || jg >= S_LEN) fm = NEG_INF;
            else fm = (amask[jg] != 0.f) ? -100000000.0f : 0.f;
            sFM[buf][t] = fm;
        }
    };

    stageKV(0, 0);
    __syncthreads();

    unsigned aq[4][4];
    {
        int m = lane >> 3, r = lane & 7;
        int qrow = warp * 16 + (m & 1) * 8 + r;
        int col0 = (m >> 1) * 8;
#pragma unroll
        for (int kk = 0; kk < 4; kk++) {
            unsigned addr = (unsigned)__cvta_generic_to_shared(&sQ[qrow * KST + kk * 16 + col0]);
            LDMATRIX_X4(aq[kk][0], aq[kk][1], aq[kk][2], aq[kk][3], addr);
        }
    }

    float o[8][4];
#pragma unroll
    for (int ni = 0; ni < 8; ni++)
#pragma unroll
        for (int j = 0; j < 4; j++) o[ni][j] = 0.f;

    float mA = NEG_INF, mB = NEG_INF, lA = 0.f, lB = 0.f;
    const int giA = i0 + warp * 16 + g;
    const int giB = giA + 8;

    for (int c9 = 0; c9 < 9; c9++) {
        const int buf = c9 & 1;
        const int jc0 = i0 - WIN + c9 * 64;
        const bool edge = (c9 == 0) || (c9 == 8);

        if (c9 < 8) {
            stageKV(c9 + 1, buf ^ 1);
            asm volatile("cp.async.wait_group 1;");
        } else {
            asm volatile("cp.async.wait_group 0;");
        }
        __syncthreads();

        float s[8][4];
#pragma unroll
        for (int ni = 0; ni < 8; ni++)
#pragma unroll
            for (int j = 0; j < 4; j++) s[ni][j] = 0.f;

        {
            int m = lane >> 3, r = lane & 7;
#pragma unroll
            for (int ni2 = 0; ni2 < 4; ni2++) {
                int krow = ni2 * 16 + (m >> 1) * 8 + r;
                int col0 = (m & 1) * 8;
                unsigned bb[4][4];
#pragma unroll
                for (int kk = 0; kk < 4; kk++) {
                    unsigned addr = (unsigned)__cvta_generic_to_shared(
                        &sK[buf][krow * KST + kk * 16 + col0]);
                    LDMATRIX_X4(bb[kk][0], bb[kk][1], bb[kk][2], bb[kk][3], addr);
                }
#pragma unroll
                for (int kk = 0; kk < 4; kk++) {
                    mma_f16(s[2 * ni2],     aq[kk], bb[kk][0], bb[kk][1]);
                    mma_f16(s[2 * ni2 + 1], aq[kk], bb[kk][2], bb[kk][3]);
                }
            }
        }

        float mxA = NEG_INF, mxB = NEG_INF;
        if (edge) {
#pragma unroll
            for (int ni = 0; ni < 8; ni++) {
                int jl0 = ni * 8 + 2 * tg;
#pragma unroll
                for (int jj = 0; jj < 2; jj++) {
                    int   gj = jc0 + jl0 + jj;
                    float fm = sFM[buf][jl0 + jj];
                    float v0 = s[ni][jj] + fm;
                    if (gj < giA - WIN || gj > giA + WIN) v0 = NEG_INF;
                    s[ni][jj] = v0;
                    mxA = fmaxf(mxA, v0);
                    float v1 = s[ni][2 + jj] + fm;
                    if (gj < giB - WIN || gj > giB + WIN) v1 = NEG_INF;
                    s[ni][2 + jj] = v1;
                    mxB = fmaxf(mxB, v1);
                }
            }
        } else {
#pragma unroll
            for (int ni = 0; ni < 8; ni++) {
                int jl0 = ni * 8 + 2 * tg;
#pragma unroll
                for (int jj = 0; jj < 2; jj++) {
                    float fm = sFM[buf][jl0 + jj];
                    float v0 = s[ni][jj] + fm;
                    s[ni][jj] = v0;
                    mxA = fmaxf(mxA, v0);
                    float v1 = s[ni][2 + jj] + fm;
                    s[ni][2 + jj] = v1;
                    mxB = fmaxf(mxB, v1);
                }
            }
        }
        mxA = fmaxf(mxA, __shfl_xor_sync(0xffffffffu, mxA, 1));
        mxA = fmaxf(mxA, __shfl_xor_sync(0xffffffffu, mxA, 2));
        mxB = fmaxf(mxB, __shfl_xor_sync(0xffffffffu, mxB, 1));
        mxB = fmaxf(mxB, __shfl_xor_sync(0xffffffffu, mxB, 2));

        float mnA = fmaxf(mA, mxA);
        float mnB = fmaxf(mB, mxB);
        float mrA = (mnA == NEG_INF) ? 0.f : mnA;
        float mrB = (mnB == NEG_INF) ? 0.f : mnB;

        unsigned ap[4][4];
        float lsA = 0.f, lsB = 0.f;
#pragma unroll
        for (int ni = 0; ni < 8; ni++) {
            float p0 = __expf(s[ni][0] - mrA);
            float p1 = __expf(s[ni][1] - mrA);
            float p2 = __expf(s[ni][2] - mrB);
            float p3 = __expf(s[ni][3] - mrB);
            unsigned uA = packh2(p0, p1);
            unsigned uB = packh2(p2, p3);
            float2 fA = __half22float2(*reinterpret_cast<__half2*>(&uA));
            float2 fB = __half22float2(*reinterpret_cast<__half2*>(&uB));
            lsA += fA.x + fA.y;
            lsB += fB.x + fB.y;
            ap[ni >> 1][(ni & 1) * 2]     = uA;
            ap[ni >> 1][(ni & 1) * 2 + 1] = uB;
        }
        lsA += __shfl_xor_sync(0xffffffffu, lsA, 1);
        lsA += __shfl_xor_sync(0xffffffffu, lsA, 2);
        lsB += __shfl_xor_sync(0xffffffffu, lsB, 1);
        lsB += __shfl_xor_sync(0xffffffffu, lsB, 2);

        float scA = __expf(mA - mrA);   // mA=-inf -> 0
        float scB = __expf(mB - mrB);
        lA = lA * scA + lsA;
        lB = lB * scB + lsB;
        mA = mnA;
        mB = mnB;
#pragma unroll
        for (int ni = 0; ni < 8; ni++) {
            o[ni][0] *= scA; o[ni][1] *= scA;
            o[ni][2] *= scB; o[ni][3] *= scB;
        }

        {
            int m = lane >> 3, r = lane & 7;
#pragma unroll
            for (int ni2 = 0; ni2 < 4; ni2++) {
                int col0 = ni2 * 16 + (m >> 1) * 8;
                unsigned bb[4][4];
#pragma unroll
                for (int kk = 0; kk < 4; kk++) {
                    int vrow = kk * 16 + (m & 1) * 8 + r;
                    unsigned addr = (unsigned)__cvta_generic_to_shared(
                        &sV[buf][vrow * KST + col0]);
                    LDMATRIX_X4_T(bb[kk][0], bb[kk][1], bb[kk][2], bb[kk][3], addr);
                }
#pragma unroll
                for (int kk = 0; kk < 4; kk++) {
                    mma_f16(o[2 * ni2],     ap[kk], bb[kk][0], bb[kk][1]);
                    mma_f16(o[2 * ni2 + 1], ap[kk], bb[kk][2], bb[kk][3]);
                }
            }
        }
        __syncthreads();
    }

    float invA = 1.f / lA;
    float invB = 1.f / lB;
    if (imask[giA]) invA = 0.f;
    if (imask[giB]) invB = 0.f;
    float* opA = out + (size_t)giA * EMB + h * HD;
    float* opB = out + (size_t)giB * EMB + h * HD;
#pragma unroll
    for (int ni = 0; ni < 8; ni++) {
        int col = ni * 8 + 2 * tg;
        float2 r0 = make_float2(o[ni][0] * invA, o[ni][1] * invA);
        float2 r1 = make_float2(o[ni][2] * invB, o[ni][3] * invB);
        *reinterpret_cast<float2*>(&opA[col]) = r0;
        *reinterpret_cast<float2*>(&opB[col]) = r1;
    }
}

// ---------------------------------------------------------------------------
extern "C" void kernel_launch(void* const* d_in, const int* in_sizes, int n_in,
                              void* d_out, int out_size)
{
    const float*         hs    = (const float*)d_in[0];
    const float*         amask = (const float*)d_in[1];
    const unsigned char* imask = (const unsigned char*)d_in[2];
    const float*         Wq    = (const float*)d_in[3];
    const float*         bq    = (const float*)d_in[4];
    const float*         Wk    = (const float*)d_in[5];
    const float*         bk    = (const float*)d_in[6];
    const float*         Wv    = (const float*)d_in[7];
    const float*         bv    = (const float*)d_in[8];
    float*               out   = (float*)d_out;

    prep_kernel<<<dim3((XA_UNITS + 255) / 256, 1, 4), 256>>>(hs, Wq, Wk, Wv);

    qkv_gemm_kernel<<<dim3(6, 32, 3), 256>>>(bq, bk, bv);

    attn_mma_kernel<<<dim3(S_LEN / 64, NHEAD), 128>>>(amask, imask, out);
}

// round 17
// speedup vs baseline: 1.6120x; 1.6120x over previous
#include <cuda_runtime.h>
#include <cuda_bf16.h>
#include <cuda_fp16.h>
#include <math_constants.h>
#include <cstdint>

#define S_LEN 4096
#define EMB   768
#define NHEAD 12
#define HD    64
#define WIN   256

// Projected Q/K/V in fp16, laid out (S, H*D) contiguous.
__device__ __half g_qh[S_LEN * EMB];
__device__ __half g_kh[S_LEN * EMB];
__device__ __half g_vh[S_LEN * EMB];

// Pre-permuted fp16 operands for the QKV GEMM (fragment-native layouts).
#define XA_UNITS (32 * 24 * 512)
__device__ uint4 g_xa[XA_UNITS];
#define WP_UNITS (3 * 12 * 24 * 256)
__device__ uint4 g_wp[WP_UNITS];

__device__ __forceinline__ void mma_f16(float c[4], const unsigned a[4],
                                        unsigned b0, unsigned b1) {
    asm volatile(
        "mma.sync.aligned.m16n8k16.row.col.f32.f16.f16.f32 "
        "{%0,%1,%2,%3}, {%4,%5,%6,%7}, {%8,%9}, {%0,%1,%2,%3};"
        : "+f"(c[0]), "+f"(c[1]), "+f"(c[2]), "+f"(c[3])
        : "r"(a[0]), "r"(a[1]), "r"(a[2]), "r"(a[3]), "r"(b0), "r"(b1));
}

__device__ __forceinline__ unsigned packh2(float lo, float hi) {
    __half2 h = __float22half2_rn(make_float2(lo, hi));
    return *reinterpret_cast<unsigned*>(&h);
}

#define LDMATRIX_X4(r0, r1, r2, r3, addr)                                      \
    asm volatile("ldmatrix.sync.aligned.m8n8.x4.shared.b16 {%0,%1,%2,%3}, [%4];" \
                 : "=r"(r0), "=r"(r1), "=r"(r2), "=r"(r3) : "r"(addr))

#define LDMATRIX_X4_T(r0, r1, r2, r3, addr)                                    \
    asm volatile("ldmatrix.sync.aligned.m8n8.x4.trans.shared.b16 {%0,%1,%2,%3}, [%4];" \
                 : "=r"(r0), "=r"(r1), "=r"(r2), "=r"(r3) : "r"(addr))

// ---------------------------------------------------------------------------
// Fused prep: z=0 -> X to A-frag layout; z=1..3 -> Wq/Wk/Wv to B-frag layout.
// ---------------------------------------------------------------------------
__global__ __launch_bounds__(256) void prep_kernel(
    const float* __restrict__ X,
    const float* __restrict__ Wq, const float* __restrict__ Wk,
    const float* __restrict__ Wv)
{
    if (blockIdx.z == 0) {
        int u = blockIdx.x * 256 + threadIdx.x;
        if (u >= XA_UNITS) return;
        int tg   = u & 3;
        int g    = (u >> 2) & 7;
        int kk2  = (u >> 5) & 1;
        int m16  = (u >> 6) & 7;
        int tile = u >> 9;
        int kb   = tile % 24;
        int mb   = tile / 24;
        int r0 = mb * 128 + m16 * 16 + g;
        int c0 = kb * 32 + kk2 * 16 + tg * 2;

        float2 x00 = *reinterpret_cast<const float2*>(&X[(size_t)r0 * EMB + c0]);
        float2 x10 = *reinterpret_cast<const float2*>(&X[(size_t)(r0 + 8) * EMB + c0]);
        float2 x01 = *reinterpret_cast<const float2*>(&X[(size_t)r0 * EMB + c0 + 8]);
        float2 x11 = *reinterpret_cast<const float2*>(&X[(size_t)(r0 + 8) * EMB + c0 + 8]);

        uint4 w;
        w.x = packh2(x00.x, x00.y);
        w.y = packh2(x10.x, x10.y);
        w.z = packh2(x01.x, x01.y);
        w.w = packh2(x11.x, x11.y);
        g_xa[u] = w;
    } else {
        const int which = blockIdx.z - 1;
        const float* W = (which == 0) ? Wq : (which == 1) ? Wk : Wv;
        int u = blockIdx.x * 256 + threadIdx.x;
        const int perW = 12 * 24 * 256;
        if (u >= perW) return;
        int tg   = u & 3;
        int g    = (u >> 2) & 7;
        int wn2  = (u >> 5) & 1;
        int half = (u >> 6) & 1;
        int kk2  = (u >> 7) & 1;
        int tile = u >> 8;
        int kb   = tile % 24;
        int nb   = tile / 24;
        int c0 = kb * 32 + kk2 * 16 + tg * 2 + half * 8;
        int n0 = nb * 64 + wn2 * 32 + g;

        const float* r0 = W + (size_t)c0 * EMB;
        const float* r1 = W + (size_t)(c0 + 1) * EMB;
        uint4 w;
        w.x = packh2(r0[n0     ], r1[n0     ]);
        w.y = packh2(r0[n0 +  8], r1[n0 +  8]);
        w.z = packh2(r0[n0 + 16], r1[n0 + 16]);
        w.w = packh2(r0[n0 + 24], r1[n0 + 24]);
        g_wp[which * perW + u] = w;
    }
}

// ---------------------------------------------------------------------------
// Fused QKV fp16 GEMM on pre-permuted operands, cp.async 2-stage pipeline
// (the measured-best R9 configuration). CTA 128x64, 8 warps = 4m x 2n,
// warp tile 32x32. Grid (12 nb, 32 mb, 3 which). fp16 epilogue.
// ---------------------------------------------------------------------------
__global__ __launch_bounds__(256) void qkv_gemm_kernel(
    const float* __restrict__ bq_, const float* __restrict__ bk_,
    const float* __restrict__ bv_)
{
    __shared__ uint4 sA[2][512];
    __shared__ uint4 sB[2][256];

    const int which = blockIdx.z;
    const float* bias = (which == 0) ? bq_ : (which == 1) ? bk_ : bv_;
    __half* out       = (which == 0) ? g_qh : (which == 1) ? g_kh : g_vh;
    const float scale = (which == 0) ? 0.125f : 1.0f;

    const int nb   = blockIdx.x;
    const int mb   = blockIdx.y;
    const int t    = threadIdx.x;
    const int lane = t & 31;
    const int wid  = t >> 5;
    const int wmg  = wid & 3;
    const int wn2  = wid >> 2;
    const int g    = lane >> 2;
    const int tg   = lane & 3;

    const uint4* xa = g_xa + (size_t)(mb * 24) * 512;
    const uint4* wp = g_wp + ((size_t)(which * 12 + nb) * 24) * 256;

    float c[2][4][4];
#pragma unroll
    for (int mi = 0; mi < 2; mi++)
#pragma unroll
        for (int ni = 0; ni < 4; ni++)
#pragma unroll
            for (int j = 0; j < 4; j++) c[mi][ni][j] = 0.f;

    auto issue_tile = [&](int kb, int s) {
        unsigned sa = (unsigned)__cvta_generic_to_shared(&sA[s][0]);
        unsigned sb = (unsigned)__cvta_generic_to_shared(&sB[s][0]);
        const uint4* asrc = xa + kb * 512;
        const uint4* bsrc = wp + kb * 256;
#pragma unroll
        for (int u = 0; u < 2; u++) {
            int i = t + u * 256;
            asm volatile("cp.async.cg.shared.global [%0], [%1], 16;"
                         :: "r"(sa + i * 16), "l"(asrc + i));
        }
        asm volatile("cp.async.cg.shared.global [%0], [%1], 16;"
                     :: "r"(sb + t * 16), "l"(bsrc + t));
        asm volatile("cp.async.commit_group;");
    };

    issue_tile(0, 0);

    const int NITER = 24;
    for (int kb = 0; kb < NITER; kb++) {
        const int s = kb & 1;
        if (kb + 1 < NITER) {
            issue_tile(kb + 1, s ^ 1);
            asm volatile("cp.async.wait_group 1;");
        } else {
            asm volatile("cp.async.wait_group 0;");
        }
        __syncthreads();

#pragma unroll
        for (int kk2 = 0; kk2 < 2; kk2++) {
            uint4 afr[2];
#pragma unroll
            for (int mi = 0; mi < 2; mi++) {
                int m16 = wmg * 2 + mi;
                afr[mi] = sA[s][((m16 * 2 + kk2) << 5) + lane];
            }
            uint4 b0 = sB[s][(((kk2 * 2 + 0) * 2 + wn2) << 5) + lane];
            uint4 b1 = sB[s][(((kk2 * 2 + 1) * 2 + wn2) << 5) + lane];
            unsigned b0a[4] = {b0.x, b0.y, b0.z, b0.w};
            unsigned b1a[4] = {b1.x, b1.y, b1.z, b1.w};
#pragma unroll
            for (int mi = 0; mi < 2; mi++) {
                const unsigned* ar = reinterpret_cast<const unsigned*>(&afr[mi]);
#pragma unroll
                for (int ni = 0; ni < 4; ni++)
                    mma_f16(c[mi][ni], ar, b0a[ni], b1a[ni]);
            }
        }
        __syncthreads();
    }

    const int bm = mb * 128;
    const int bn = nb * 64;
#pragma unroll
    for (int mi = 0; mi < 2; mi++)
#pragma unroll
        for (int ni = 0; ni < 4; ni++) {
            int row = bm + wmg * 32 + mi * 16 + g;
            int col = bn + wn2 * 32 + ni * 8 + 2 * tg;
            float b0 = bias[col], b1 = bias[col + 1];
            unsigned h0 = packh2((c[mi][ni][0] + b0) * scale, (c[mi][ni][1] + b1) * scale);
            unsigned h1 = packh2((c[mi][ni][2] + b0) * scale, (c[mi][ni][3] + b1) * scale);
            *reinterpret_cast<unsigned*>(&out[(size_t)row * EMB + col])       = h0;
            *reinterpret_cast<unsigned*>(&out[(size_t)(row + 8) * EMB + col]) = h1;
        }
}

// ---------------------------------------------------------------------------
// fp16 tensor-core banded flash attention: 64 queries x 1 head per CTA,
// 128 threads; edge specialization (window compares only for c9 == 0/8).
// ---------------------------------------------------------------------------
#define KST 72  // smem row stride in halves

__global__ __launch_bounds__(128) void attn_mma_kernel(
    const float* __restrict__ amask, const unsigned char* __restrict__ imask,
    float* __restrict__ out)
{
    __shared__ __half sQ[64 * KST];
    __shared__ __half sK[2][64 * KST];
    __shared__ __half sV[2][64 * KST];
    __shared__ float  sFM[2][64];

    const int i0   = blockIdx.x * 64;
    const int h    = blockIdx.y;
    const int t    = threadIdx.x;
    const int lane = t & 31;
    const int warp = t >> 5;
    const int g    = lane >> 2;
    const int tg   = lane & 3;
    const float NEG_INF = -CUDART_INF_F;

#pragma unroll
    for (int u = 0; u < 4; u++) {
        int vv = t + u * 128;
        int r = vv >> 3, w = vv & 7;
        uint4 q = *reinterpret_cast<const uint4*>(&g_qh[(size_t)(i0 + r) * EMB + h * HD + w * 8]);
        *reinterpret_cast<uint4*>(&sQ[r * KST + w * 8]) = q;
    }

    auto stageKV = [&](int c9, int buf) {
        int jc0 = i0 - WIN + c9 * 64;
#pragma unroll
        for (int u = 0; u < 4; u++) {
            int vv = t + u * 128;
            int r = vv >> 3, w = vv & 7;
            int jg = jc0 + r;
            bool ok = (jg >= 0 && jg < S_LEN);
            size_t src = ok ? ((size_t)jg * EMB + h * HD + w * 8) : 0;
            int sz = ok ? 16 : 0;
            unsigned kd = (unsigned)__cvta_generic_to_shared(&sK[buf][r * KST + w * 8]);
            unsigned vd = (unsigned)__cvta_generic_to_shared(&sV[buf][r * KST + w * 8]);
            asm volatile("cp.async.cg.shared.global [%0], [%1], 16, %2;"
                         :: "r"(kd), "l"(g_kh + src), "r"(sz));
            asm volatile("cp.async.cg.shared.global [%0], [%1], 16, %2;"
                         :: "r"(vd), "l"(g_vh + src), "r"(sz));
        }
        asm volatile("cp.async.commit_group;");
        if (t < 64) {
            int jg = jc0 + t;
            float fm;
            if (jg < 0 || jg >= S_LEN) fm = NEG_INF;
            else fm = (amask[jg] != 0.f) ? -100000000.0f : 0.f;
            sFM[buf][t] = fm;
        }
    };

    stageKV(0, 0);
    __syncthreads();

    unsigned aq[4][4];
    {
        int m = lane >> 3, r = lane & 7;
        int qrow = warp * 16 + (m & 1) * 8 + r;
        int col0 = (m >> 1) * 8;
#pragma unroll
        for (int kk = 0; kk < 4; kk++) {
            unsigned addr = (unsigned)__cvta_generic_to_shared(&sQ[qrow * KST + kk * 16 + col0]);
            LDMATRIX_X4(aq[kk][0], aq[kk][1], aq[kk][2], aq[kk][3], addr);
        }
    }

    float o[8][4];
#pragma unroll
    for (int ni = 0; ni < 8; ni++)
#pragma unroll
        for (int j = 0; j < 4; j++) o[ni][j] = 0.f;

    float mA = NEG_INF, mB = NEG_INF, lA = 0.f, lB = 0.f;
    const int giA = i0 + warp * 16 + g;
    const int giB = giA + 8;

    for (int c9 = 0; c9 < 9; c9++) {
        const int buf = c9 & 1;
        const int jc0 = i0 - WIN + c9 * 64;
        const bool edge = (c9 == 0) || (c9 == 8);

        if (c9 < 8) {
            stageKV(c9 + 1, buf ^ 1);
            asm volatile("cp.async.wait_group 1;");
        } else {
            asm volatile("cp.async.wait_group 0;");
        }
        __syncthreads();

        float s[8][4];
#pragma unroll
        for (int ni = 0; ni < 8; ni++)
#pragma unroll
            for (int j = 0; j < 4; j++) s[ni][j] = 0.f;

        {
            int m = lane >> 3, r = lane & 7;
#pragma unroll
            for (int ni2 = 0; ni2 < 4; ni2++) {
                int krow = ni2 * 16 + (m >> 1) * 8 + r;
                int col0 = (m & 1) * 8;
                unsigned bb[4][4];
#pragma unroll
                for (int kk = 0; kk < 4; kk++) {
                    unsigned addr = (unsigned)__cvta_generic_to_shared(
                        &sK[buf][krow * KST + kk * 16 + col0]);
                    LDMATRIX_X4(bb[kk][0], bb[kk][1], bb[kk][2], bb[kk][3], addr);
                }
#pragma unroll
                for (int kk = 0; kk < 4; kk++) {
                    mma_f16(s[2 * ni2],     aq[kk], bb[kk][0], bb[kk][1]);
                    mma_f16(s[2 * ni2 + 1], aq[kk], bb[kk][2], bb[kk][3]);
                }
            }
        }

        float mxA = NEG_INF, mxB = NEG_INF;
        if (edge) {
#pragma unroll
            for (int ni = 0; ni < 8; ni++) {
                int jl0 = ni * 8 + 2 * tg;
#pragma unroll
                for (int jj = 0; jj < 2; jj++) {
                    int   gj = jc0 + jl0 + jj;
                    float fm = sFM[buf][jl0 + jj];
                    float v0 = s[ni][jj] + fm;
                    if (gj < giA - WIN || gj > giA + WIN) v0 = NEG_INF;
                    s[ni][jj] = v0;
                    mxA = fmaxf(mxA, v0);
                    float v1 = s[ni][2 + jj] + fm;
                    if (gj < giB - WIN || gj > giB + WIN) v1 = NEG_INF;
                    s[ni][2 + jj] = v1;
                    mxB = fmaxf(mxB, v1);
                }
            }
        } else {
#pragma unroll
            for (int ni = 0; ni < 8; ni++) {
                int jl0 = ni * 8 + 2 * tg;
#pragma unroll
                for (int jj = 0; jj < 2; jj++) {
                    float fm = sFM[buf][jl0 + jj];
                    float v0 = s[ni][jj] + fm;
                    s[ni][jj] = v0;
                    mxA = fmaxf(mxA, v0);
                    float v1 = s[ni][2 + jj] + fm;
                    s[ni][2 + jj] = v1;
                    mxB = fmaxf(mxB, v1);
                }
            }
        }
        mxA = fmaxf(mxA, __shfl_xor_sync(0xffffffffu, mxA, 1));
        mxA = fmaxf(mxA, __shfl_xor_sync(0xffffffffu, mxA, 2));
        mxB = fmaxf(mxB, __shfl_xor_sync(0xffffffffu, mxB, 1));
        mxB = fmaxf(mxB, __shfl_xor_sync(0xffffffffu, mxB, 2));

        float mnA = fmaxf(mA, mxA);
        float mnB = fmaxf(mB, mxB);
        float mrA = (mnA == NEG_INF) ? 0.f : mnA;
        float mrB = (mnB == NEG_INF) ? 0.f : mnB;

        unsigned ap[4][4];
        float lsA = 0.f, lsB = 0.f;
#pragma unroll
        for (int ni = 0; ni < 8; ni++) {
            float p0 = __expf(s[ni][0] - mrA);
            float p1 = __expf(s[ni][1] - mrA);
            float p2 = __expf(s[ni][2] - mrB);
            float p3 = __expf(s[ni][3] - mrB);
            unsigned uA = packh2(p0, p1);
            unsigned uB = packh2(p2, p3);
            float2 fA = __half22float2(*reinterpret_cast<__half2*>(&uA));
            float2 fB = __half22float2(*reinterpret_cast<__half2*>(&uB));
            lsA += fA.x + fA.y;
            lsB += fB.x + fB.y;
            ap[ni >> 1][(ni & 1) * 2]     = uA;
            ap[ni >> 1][(ni & 1) * 2 + 1] = uB;
        }
        lsA += __shfl_xor_sync(0xffffffffu, lsA, 1);
        lsA += __shfl_xor_sync(0xffffffffu, lsA, 2);
        lsB += __shfl_xor_sync(0xffffffffu, lsB, 1);
        lsB += __shfl_xor_sync(0xffffffffu, lsB, 2);

        float scA = __expf(mA - mrA);   // mA=-inf -> 0
        float scB = __expf(mB - mrB);
        lA = lA * scA + lsA;
        lB = lB * scB + lsB;
        mA = mnA;
        mB = mnB;
#pragma unroll
        for (int ni = 0; ni < 8; ni++) {
            o[ni][0] *= scA; o[ni][1] *= scA;
            o[ni][2] *= scB; o[ni][3] *= scB;
        }

        {
            int m = lane >> 3, r = lane & 7;
#pragma unroll
            for (int ni2 = 0; ni2 < 4; ni2++) {
                int col0 = ni2 * 16 + (m >> 1) * 8;
                unsigned bb[4][4];
#pragma unroll
                for (int kk = 0; kk < 4; kk++) {
                    int vrow = kk * 16 + (m & 1) * 8 + r;
                    unsigned addr = (unsigned)__cvta_generic_to_shared(
                        &sV[buf][vrow * KST + col0]);
                    LDMATRIX_X4_T(bb[kk][0], bb[kk][1], bb[kk][2], bb[kk][3], addr);
                }
#pragma unroll
                for (int kk = 0; kk < 4; kk++) {
                    mma_f16(o[2 * ni2],     ap[kk], bb[kk][0], bb[kk][1]);
                    mma_f16(o[2 * ni2 + 1], ap[kk], bb[kk][2], bb[kk][3]);
                }
            }
        }
        __syncthreads();
    }

    float invA = 1.f / lA;
    float invB = 1.f / lB;
    if (imask[giA]) invA = 0.f;
    if (imask[giB]) invB = 0.f;
    float* opA = out + (size_t)giA * EMB + h * HD;
    float* opB = out + (size_t)giB * EMB + h * HD;
#pragma unroll
    for (int ni = 0; ni < 8; ni++) {
        int col = ni * 8 + 2 * tg;
        float2 r0 = make_float2(o[ni][0] * invA, o[ni][1] * invA);
        float2 r1 = make_float2(o[ni][2] * invB, o[ni][3] * invB);
        *reinterpret_cast<float2*>(&opA[col]) = r0;
        *reinterpret_cast<float2*>(&opB[col]) = r1;
    }
}

// ---------------------------------------------------------------------------
extern "C" void kernel_launch(void* const* d_in, const int* in_sizes, int n_in,
                              void* d_out, int out_size)
{
    const float*         hs    = (const float*)d_in[0];
    const float*         amask = (const float*)d_in[1];
    const unsigned char* imask = (const unsigned char*)d_in[2];
    const float*         Wq    = (const float*)d_in[3];
    const float*         bq    = (const float*)d_in[4];
    const float*         Wk    = (const float*)d_in[5];
    const float*         bk    = (const float*)d_in[6];
    const float*         Wv    = (const float*)d_in[7];
    const float*         bv    = (const float*)d_in[8];
    float*               out   = (float*)d_out;

    prep_kernel<<<dim3((XA_UNITS + 255) / 256, 1, 4), 256>>>(hs, Wq, Wk, Wv);

    qkv_gemm_kernel<<<dim3(12, 32, 3), 256>>>(bq, bk, bv);

    attn_mma_kernel<<<dim3(S_LEN / 64, NHEAD), 128>>>(amask, imask, out);
}